// round 12
// baseline (speedup 1.0000x reference)
#include <cuda_runtime.h>
#include <cuda_bf16.h>
#include <math_constants.h>

// Problem constants
#define B_  4
#define TE_ 1024
#define TD_ 512
#define H_  128

#define DT_ 4        // decoder steps per block
#define THREADS2 256 // 8 warps

// Scratch: transposed encoder projection wsT[b][q][t][c]  (q = h/4 group, c = h%4)
__device__ float g_WsT[B_ * TE_ * H_];
__device__ float g_Uh [B_ * TD_ * H_]; // [B,TD,H]

__device__ __forceinline__ float tanhfast(float x) {
    float y;
    asm("tanh.approx.f32 %0, %1;" : "=f"(y) : "f"(x));
    return y;
}

// packed f32x2 helpers (Blackwell)
__device__ __forceinline__ unsigned long long pk2(float lo, float hi) {
    unsigned long long r;
    asm("mov.b64 %0, {%1, %2};" : "=l"(r) : "f"(lo), "f"(hi));
    return r;
}
__device__ __forceinline__ unsigned long long fma2(unsigned long long a,
                                                   unsigned long long b,
                                                   unsigned long long c) {
    unsigned long long d;
    asm("fma.rn.f32x2 %0, %1, %2, %3;" : "=l"(d) : "l"(a), "l"(b), "l"(c));
    return d;
}
__device__ __forceinline__ void upk2(unsigned long long v, float& lo, float& hi) {
    asm("mov.b64 {%0, %1}, %2;" : "=f"(lo), "=f"(hi) : "l"(v));
}

// ---------------------------------------------------------------------------
// Kernel 1: projections.  enc @ W_a -> g_WsT (transposed), dec @ U_a -> g_Uh.
// 16 rows per block, 256 threads: thread = (half, col); half rh does rows
// rh*8..rh*8+7.  Halves the number of blocks (and W-matrix L2 reads).
// ---------------------------------------------------------------------------
__global__ __launch_bounds__(256)
void proj_kernel(const float* __restrict__ enc,
                 const float* __restrict__ dec,
                 const float* __restrict__ Wa,
                 const float* __restrict__ Ua)
{
    __shared__ float xs[16][128];
    const int bid = blockIdx.x;
    const int t   = threadIdx.x & 127;   // column
    const int rh  = threadIdx.x >> 7;    // row half (0/1)

    const bool is_ws = (bid < (B_ * TE_ / 16));           // 256 blocks
    const float* x = is_ws ? enc : dec;
    const float* M = is_ws ? Wa  : Ua;
    const int row0 = (is_ws ? bid * 16 : (bid - (B_ * TE_ / 16)) * 16);

#pragma unroll
    for (int r = 0; r < 8; ++r)
        xs[rh * 8 + r][t] = x[(size_t)(row0 + rh * 8 + r) * H_ + t];
    __syncthreads();

    float acc[8];
#pragma unroll
    for (int r = 0; r < 8; ++r) acc[r] = 0.f;

#pragma unroll 4
    for (int h = 0; h < H_; ++h) {
        const float w = M[h * H_ + t];
#pragma unroll
        for (int r = 0; r < 8; ++r)
            acc[r] = fmaf(xs[rh * 8 + r][h], w, acc[r]);
    }

    if (is_ws) {
        const int q = t >> 2, c = t & 3;
#pragma unroll
        for (int r = 0; r < 8; ++r) {
            const int grow = row0 + rh * 8 + r;
            const int bb = grow >> 10;
            const int tt = grow & (TE_ - 1);
            g_WsT[((size_t)(bb * 32 + q) * TE_ + tt) * 4 + c] = acc[r];
        }
    } else {
#pragma unroll
        for (int r = 0; r < 8; ++r)
            g_Uh[(size_t)(row0 + rh * 8 + r) * H_ + t] = acc[r];
    }
}

// ---------------------------------------------------------------------------
// Kernel 2: fused energies + shift-free softmax + context.
// Grid (TD_/DT_, B_), 256 threads (8 warps), 4 blocks/SM.
// ---------------------------------------------------------------------------
__global__ __launch_bounds__(THREADS2, 4)
void attn_kernel(const float* __restrict__ enc,
                 const float* __restrict__ Va,
                 float* __restrict__ c_out,  // [B,TD,H]
                 float* __restrict__ e_out)  // [B,TD,TE]
{
    extern __shared__ char smem_raw[];
    float4* uh4   = (float4*)smem_raw;                       // 128 f4 = 2048 B
    float4* v4s   = (float4*)(smem_raw + 2048);              //  32 f4 =  512 B
    float*  esf   = (float*) (smem_raw + 2560);              // [1024][4] = 16384 B
    float4* cp    = (float4*)(smem_raw + 2560 + 16384);      // [8][4][32] = 16384 B
    float*  redsm = (float*) (smem_raw + 2560 + 32768);      // [8][4] = 128 B
    float*  invs  = (float*) (smem_raw + 2560 + 32768 + 128);// [4]

    const int b    = blockIdx.y;
    const int d0   = blockIdx.x * DT_;
    const int tid  = threadIdx.x;
    const int lane = tid & 31;
    const int warp = tid >> 5;

    // stage U_h (4 rows x 128) and V (128)
    if (tid < DT_ * 32) {
        const float4* uh_src = (const float4*)(g_Uh + ((size_t)b * TD_ + d0) * H_);
        uh4[tid] = uh_src[tid];
    }
    if (tid >= 128 && tid < 160) v4s[tid - 128] = ((const float4*)Va)[tid - 128];
    __syncthreads();

    // ----- Phase A: energies (MUFU-roofline; unchanged) -----
    float acc[4][4];
#pragma unroll
    for (int c2 = 0; c2 < 4; ++c2)
#pragma unroll
        for (int dd = 0; dd < DT_; ++dd) acc[c2][dd] = 0.f;

    {
        const float4* wsT4 = (const float4*)g_WsT + (size_t)b * 32 * TE_;
#pragma unroll 1
        for (int q = 0; q < 32; ++q) {
            const float4 vv = v4s[q];
            const float4 u0 = uh4[q];
            const float4 u1 = uh4[32 + q];
            const float4 u2 = uh4[64 + q];
            const float4 u3 = uh4[96 + q];
            const float4* wrow = wsT4 + (size_t)q * TE_;
#pragma unroll
            for (int c2 = 0; c2 < 4; ++c2) {
                const int t = (warp + c2 * 8) * 32 + lane;
                const float4 wv = wrow[t];             // coalesced LDG.128 (L2)
                acc[c2][0] = fmaf(vv.x, tanhfast(wv.x + u0.x), acc[c2][0]);
                acc[c2][0] = fmaf(vv.y, tanhfast(wv.y + u0.y), acc[c2][0]);
                acc[c2][0] = fmaf(vv.z, tanhfast(wv.z + u0.z), acc[c2][0]);
                acc[c2][0] = fmaf(vv.w, tanhfast(wv.w + u0.w), acc[c2][0]);
                acc[c2][1] = fmaf(vv.x, tanhfast(wv.x + u1.x), acc[c2][1]);
                acc[c2][1] = fmaf(vv.y, tanhfast(wv.y + u1.y), acc[c2][1]);
                acc[c2][1] = fmaf(vv.z, tanhfast(wv.z + u1.z), acc[c2][1]);
                acc[c2][1] = fmaf(vv.w, tanhfast(wv.w + u1.w), acc[c2][1]);
                acc[c2][2] = fmaf(vv.x, tanhfast(wv.x + u2.x), acc[c2][2]);
                acc[c2][2] = fmaf(vv.y, tanhfast(wv.y + u2.y), acc[c2][2]);
                acc[c2][2] = fmaf(vv.z, tanhfast(wv.z + u2.z), acc[c2][2]);
                acc[c2][2] = fmaf(vv.w, tanhfast(wv.w + u2.w), acc[c2][2]);
                acc[c2][3] = fmaf(vv.x, tanhfast(wv.x + u3.x), acc[c2][3]);
                acc[c2][3] = fmaf(vv.y, tanhfast(wv.y + u3.y), acc[c2][3]);
                acc[c2][3] = fmaf(vv.z, tanhfast(wv.z + u3.z), acc[c2][3]);
                acc[c2][3] = fmaf(vv.w, tanhfast(wv.w + u3.w), acc[c2][3]);
            }
        }
    }

    // exp (shift-free: |e| <= sum|V| ~ 5.2, no overflow) + store + partial sums
    float s0 = 0.f, s1 = 0.f, s2 = 0.f, s3 = 0.f;
#pragma unroll
    for (int c2 = 0; c2 < 4; ++c2) {
        const int t = (warp + c2 * 8) * 32 + lane;
        const float e0 = __expf(acc[c2][0]);
        const float e1 = __expf(acc[c2][1]);
        const float e2 = __expf(acc[c2][2]);
        const float e3 = __expf(acc[c2][3]);
        ((float4*)esf)[t] = make_float4(e0, e1, e2, e3);
        s0 += e0; s1 += e1; s2 += e2; s3 += e3;
    }
#pragma unroll
    for (int o = 16; o > 0; o >>= 1) {
        s0 += __shfl_xor_sync(0xffffffffu, s0, o);
        s1 += __shfl_xor_sync(0xffffffffu, s1, o);
        s2 += __shfl_xor_sync(0xffffffffu, s2, o);
        s3 += __shfl_xor_sync(0xffffffffu, s3, o);
    }
    if (lane == 0) {
        redsm[warp * 4 + 0] = s0;
        redsm[warp * 4 + 1] = s1;
        redsm[warp * 4 + 2] = s2;
        redsm[warp * 4 + 3] = s3;
    }
    __syncthreads();
    if (tid < 4) {
        float s = 0.f;
#pragma unroll
        for (int w = 0; w < 8; ++w) s += redsm[w * 4 + tid];
        invs[tid] = 1.f / s;
    }
    __syncthreads();

    // ----- e_out write: one conflict-free pass, thread owns one t -----
    {
        const float i0 = invs[0], i1 = invs[1], i2 = invs[2], i3 = invs[3];
        float* eo = e_out + ((size_t)b * TD_ + d0) * TE_;
#pragma unroll
        for (int c2 = 0; c2 < 4; ++c2) {
            const int t = c2 * THREADS2 + tid;
            const float4 e4 = ((const float4*)esf)[t];   // conflict-free LDS.128
            eo[t]            = e4.x * i0;
            eo[TE_ + t]      = e4.y * i1;
            eo[2 * TE_ + t]  = e4.z * i2;
            eo[3 * TE_ + t]  = e4.w * i3;
        }
    }

    // ----- Phase C: context with unnormalized weights, packed f32x2 FMA -----
    unsigned long long a00 = 0ull, a01 = 0ull;   // dd=0: h pairs 01, 23
    unsigned long long a10 = 0ull, a11 = 0ull;
    unsigned long long a20 = 0ull, a21 = 0ull;
    unsigned long long a30 = 0ull, a31 = 0ull;

    const float4* encb = (const float4*)(enc + (size_t)b * TE_ * H_);
    const float4* es4  = (const float4*)esf;
    for (int t0 = warp * 8; t0 < TE_; t0 += 64) {
#pragma unroll
        for (int r = 0; r < 8; ++r) {
            const int t = t0 + r;
            const float4 ev = encb[(size_t)t * 32 + lane];   // coalesced LDG.128
            const float4 e4 = es4[t];                        // broadcast LDS.128
            const unsigned long long ev01 = pk2(ev.x, ev.y);
            const unsigned long long ev23 = pk2(ev.z, ev.w);
            const unsigned long long w0 = pk2(e4.x, e4.x);
            const unsigned long long w1 = pk2(e4.y, e4.y);
            const unsigned long long w2 = pk2(e4.z, e4.z);
            const unsigned long long w3 = pk2(e4.w, e4.w);
            a00 = fma2(w0, ev01, a00);  a01 = fma2(w0, ev23, a01);
            a10 = fma2(w1, ev01, a10);  a11 = fma2(w1, ev23, a11);
            a20 = fma2(w2, ev01, a20);  a21 = fma2(w2, ev23, a21);
            a30 = fma2(w3, ev01, a30);  a31 = fma2(w3, ev23, a31);
        }
    }

    // unpack into cp
    {
        float4 c0, c1, c2v, c3;
        upk2(a00, c0.x, c0.y);   upk2(a01, c0.z, c0.w);
        upk2(a10, c1.x, c1.y);   upk2(a11, c1.z, c1.w);
        upk2(a20, c2v.x, c2v.y); upk2(a21, c2v.z, c2v.w);
        upk2(a30, c3.x, c3.y);   upk2(a31, c3.z, c3.w);
        cp[(warp * 4 + 0) * 32 + lane] = c0;
        cp[(warp * 4 + 1) * 32 + lane] = c1;
        cp[(warp * 4 + 2) * 32 + lane] = c2v;
        cp[(warp * 4 + 3) * 32 + lane] = c3;
    }
    __syncthreads();

    if (tid < 128) {
        const int dd = tid >> 5;
        const int hq = tid & 31;
        const float inv = invs[dd];
        float4 s = make_float4(0.f,0.f,0.f,0.f);
#pragma unroll
        for (int w = 0; w < 8; ++w) {
            const float4 p = cp[(w * 4 + dd) * 32 + hq];
            s.x += p.x; s.y += p.y; s.z += p.z; s.w += p.w;
        }
        s.x *= inv; s.y *= inv; s.z *= inv; s.w *= inv;
        float4* co = (float4*)(c_out + ((size_t)b * TD_ + d0 + dd) * H_);
        co[hq] = s;
    }
}

// ---------------------------------------------------------------------------
extern "C" void kernel_launch(void* const* d_in, const int* in_sizes, int n_in,
                              void* d_out, int out_size)
{
    const float* enc = (const float*)d_in[0];   // [B,TE,H]
    const float* dec = (const float*)d_in[1];   // [B,TD,H]
    const float* Wa  = (const float*)d_in[2];   // [H,H]
    const float* Ua  = (const float*)d_in[3];   // [H,H]
    const float* Va  = (const float*)d_in[4];   // [H,1]

    float* c_out = (float*)d_out;                       // [B,TD,H]
    float* e_out = c_out + (size_t)B_ * TD_ * H_;       // [B,TD,TE]

    const int smem_bytes = 2048 + 512 + 16384 + 16384 + 128 + 16;
    cudaFuncSetAttribute(attn_kernel,
                         cudaFuncAttributeMaxDynamicSharedMemorySize,
                         smem_bytes);

    // 256 blocks for WsT + 128 for Uh, 16 rows each
    proj_kernel<<<(B_ * TE_ / 16) + (B_ * TD_ / 16), 256>>>(enc, dec, Wa, Ua);

    dim3 grid(TD_ / DT_, B_);
    attn_kernel<<<grid, THREADS2, smem_bytes>>>(enc, Va, c_out, e_out);
}